// round 5
// baseline (speedup 1.0000x reference)
#include <cuda_runtime.h>
#include <cstdint>
#include <math_constants.h>

#define BB 16
#define NPTS 4096

// ---------------- scratch (static device globals; no allocation) ----------------
__device__ __align__(16) int   g_sidx1[BB * 512];
__device__ __align__(16) float g_xyz2[BB * 512 * 3];
__device__ __align__(16) float g_grp1[BB * 9 * 512 * 32];
__device__ __align__(16) float g_h1[BB * 64 * 512 * 32];
__device__ __align__(16) float g_feat2[BB * 128 * 512];
__device__ __align__(16) int   g_sidx2[BB * 64];
__device__ __align__(16) float g_xyz3[BB * 64 * 3];
__device__ __align__(16) float g_grp2[BB * 131 * 64 * 64];
__device__ __align__(16) float g_h2[BB * 128 * 64 * 64];
__device__ __align__(16) float g_feat3[BB * 256 * 64];
__device__ __align__(16) int   g_sidx3[BB * 1];
__device__ __align__(16) float g_xyz4[BB * 3];
__device__ __align__(16) float g_grp3[BB * 259 * 64];
__device__ __align__(16) float g_h3[BB * 512 * 64];
__device__ __align__(16) float g_feat4[BB * 1024];
__device__ __align__(16) float g_c1[BB * 1024];
__device__ __align__(16) float g_c2[BB * 512];
__device__ __align__(16) float g_c3[BB * 128];
// duplicated weights (for f32x2 broadcast operand)
__device__ __align__(16) float g_wdup[1500000];

#define WD0 0          // SA1-L2: 64x128  -> 16384
#define WD1 16384      // SA2-L1: 131x128 -> 33536
#define WD2 49920      // SA2-L2: 128x256 -> 65536
#define WD3 115456     // SA3-L1: 259x512 -> 265216
#define WD4 380672     // SA3-L2: 512x1024-> 1048576

// ---------------- small helpers ----------------
__device__ __forceinline__ uint32_t smem_u32(const void* p) {
    return (uint32_t)__cvta_generic_to_shared(p);
}
__device__ __forceinline__ void cp16(uint32_t dst, const void* src, bool v) {
    asm volatile("cp.async.ca.shared.global [%0], [%1], 16, %2;"
                 :: "r"(dst), "l"(src), "r"(v ? 16 : 0));
}
__device__ __forceinline__ void cp_commit() {
    asm volatile("cp.async.commit_group;");
}
template <int N>
__device__ __forceinline__ void cp_wait() {
    asm volatile("cp.async.wait_group %0;" :: "n"(N));
}
__device__ __forceinline__ void fma2(unsigned long long& d, unsigned long long a,
                                     unsigned long long b) {
    asm("fma.rn.f32x2 %0, %1, %2, %0;" : "+l"(d) : "l"(a), "l"(b));
}
__device__ __forceinline__ float u64lo(unsigned long long v) {
    return __uint_as_float((uint32_t)v);
}
__device__ __forceinline__ float u64hi(unsigned long long v) {
    return __uint_as_float((uint32_t)(v >> 32));
}

// ---------------- merged weight duplication: Wd[c][2o]=Wd[c][2o+1]=W[o][c] ---------
__global__ void dup_all_kernel(const float* __restrict__ w0, const float* __restrict__ w1,
                               const float* __restrict__ w2, const float* __restrict__ w3,
                               const float* __restrict__ w4, float* __restrict__ wd) {
    int i = blockIdx.x * 256 + threadIdx.x;
    const float* W;
    int Cin, Cout, off;
    if (i < 8192)        { W = w0; Cin = 64;  Cout = 128;  off = WD0; }
    else if (i < 24960)  { W = w1; Cin = 131; Cout = 128;  off = WD1; i -= 8192; }
    else if (i < 57728)  { W = w2; Cin = 128; Cout = 256;  off = WD2; i -= 24960; }
    else if (i < 190336) { W = w3; Cin = 259; Cout = 512;  off = WD3; i -= 57728; }
    else if (i < 714624) { W = w4; Cin = 512; Cout = 1024; off = WD4; i -= 190336; }
    else return;
    int c = i / Cout, o = i - c * Cout;
    float v = W[(size_t)o * Cin + c];
    float* d = g_wdup + off + (size_t)c * (2 * Cout) + 2 * o;
    d[0] = v;
    d[1] = v;
}

// ---------------- furthest point sampling ----------------
// Single barrier per iteration: warp REDUX -> shared u64 atomicMax of
// pack = (dist_bits << 32) | (0xFFFFFFFF - idx); 3-slot parity ring avoids
// reset/read races. Exact JAX arithmetic; tie-break = smallest index.
template <int ITEMS>
__global__ void fps_kernel(const float* __restrict__ xyz, int xst, int N, int npoint,
                           int* __restrict__ out) {
    const int b = blockIdx.x;
    const float* px = xyz + (size_t)b * N * xst;
    const int tid = threadIdx.x;

    float lx[ITEMS], ly[ITEMS], lz[ITEMS], ld[ITEMS];
#pragma unroll
    for (int i = 0; i < ITEMS; i++) {
        int n = tid + i * 512;
        if (n < N) {
            lx[i] = px[n * xst + 0];
            ly[i] = px[n * xst + 1];
            lz[i] = px[n * xst + 2];
            ld[i] = 1e10f;
        } else {
            ld[i] = -1.0f;
        }
    }

    __shared__ unsigned long long sbuf[3];
    if (tid < 3) sbuf[tid] = 0ull;
    __syncthreads();

    int far = 0;
    for (int it = 0; it < npoint; it++) {
        if (it > 0)
            far = (int)(0xFFFFFFFFu - (unsigned)(sbuf[(it - 1) % 3] & 0xFFFFFFFFull));
        if (tid == 0) {
            out[b * npoint + it] = far;
            sbuf[(it + 1) % 3] = 0ull;  // slot last read before barrier B(it-1)
        }
        float cx = px[far * xst + 0];
        float cy = px[far * xst + 1];
        float cz = px[far * xst + 2];

        float bv = -1.0f;
        int bi = 0;
#pragma unroll
        for (int i = 0; i < ITEMS; i++) {
            int n = tid + i * 512;
            if (n < N) {
                float dx = __fsub_rn(lx[i], cx);
                float dy = __fsub_rn(ly[i], cy);
                float dz = __fsub_rn(lz[i], cz);
                float d = __fadd_rn(__fadd_rn(__fmul_rn(dx, dx), __fmul_rn(dy, dy)),
                                    __fmul_rn(dz, dz));
                float nd = fminf(ld[i], d);
                ld[i] = nd;
                if (nd > bv) { bv = nd; bi = n; }  // ascending n -> first-max kept
            }
        }
        // dists nonneg -> float bits order-preserving
        unsigned ub = (tid < N) ? __float_as_uint(bv) : 0u;
        unsigned wmax = __reduce_max_sync(0xffffffffu, ub);
        unsigned uidx = (tid < N && ub == wmax) ? (unsigned)bi : 0xffffffffu;
        unsigned wimin = __reduce_min_sync(0xffffffffu, uidx);
        if ((tid & 31) == 0)
            atomicMax(&sbuf[it % 3],
                      ((unsigned long long)wmax << 32) |
                          (unsigned long long)(0xFFFFFFFFu - wimin));
        __syncthreads();
    }
}

// ---------------- ball query + gather/group ----------------
__global__ void bq_group_kernel(const float* __restrict__ xyzp, int xst,
                                const int* __restrict__ sidx,
                                const float* __restrict__ fbase,
                                size_t f_bs, int f_cs, int f_js,
                                float* __restrict__ new_xyz, float* __restrict__ grp,
                                int N, int S, int K, int Cf, float r2) {
    const int b = blockIdx.y, s = blockIdx.x;
    const float* px = xyzp + (size_t)b * N * xst;
    const int ci = sidx[b * S + s];
    const float cx = px[ci * xst + 0];
    const float cy = px[ci * xst + 1];
    const float cz = px[ci * xst + 2];
    const int tid = threadIdx.x;

    __shared__ int sIdx[64];

    if (tid == 0) {
        new_xyz[((size_t)b * S + s) * 3 + 0] = cx;
        new_xyz[((size_t)b * S + s) * 3 + 1] = cy;
        new_xyz[((size_t)b * S + s) * 3 + 2] = cz;
    }

    if (tid < 32) {
        int cnt = 0, first = -1;
        for (int base = 0; base < N; base += 32) {
            int j = base + tid;
            bool pred = false;
            if (j < N) {
                float dx = __fsub_rn(cx, px[j * xst + 0]);
                float dy = __fsub_rn(cy, px[j * xst + 1]);
                float dz = __fsub_rn(cz, px[j * xst + 2]);
                float d2 = __fadd_rn(__fadd_rn(__fmul_rn(dx, dx), __fmul_rn(dy, dy)),
                                     __fmul_rn(dz, dz));
                pred = (d2 < r2);
            }
            unsigned m = __ballot_sync(0xffffffffu, pred);
            if (first < 0 && m) first = base + __ffs(m) - 1;
            if (pred) {
                int pos = cnt + __popc(m & ((1u << tid) - 1u));
                if (pos < K) sIdx[pos] = j;
            }
            cnt += __popc(m);
            if (cnt >= K) break;
        }
        int fillv = (first < 0) ? 0 : first;
        for (int k = cnt + tid; k < K; k += 32) sIdx[k] = fillv;
    }
    __syncthreads();

    const int C = 3 + Cf;
    const size_t SK = (size_t)S * K;
    const size_t pbase = (size_t)s * K;
    for (int e = tid; e < C * K; e += blockDim.x) {
        int ch = e / K, k = e - ch * K;
        int j = sIdx[k];
        float v;
        if (ch == 0)      v = __fsub_rn(px[j * xst + 0], cx);
        else if (ch == 1) v = __fsub_rn(px[j * xst + 1], cy);
        else if (ch == 2) v = __fsub_rn(px[j * xst + 2], cz);
        else              v = fbase[(size_t)b * f_bs + (size_t)(ch - 3) * f_cs +
                                    (size_t)j * f_js];
        grp[((size_t)b * C + ch) * SK + pbase + k] = v;
    }
}

// ---------------- SA1 layer1: 9 -> 64 streaming conv + BN + ReLU ----------------
__global__ void conv9_kernel(const float* __restrict__ x, const float* __restrict__ W,
                             const float* __restrict__ g, const float* __restrict__ bi,
                             float* __restrict__ out, int P) {
    __shared__ float ws[64 * 9];
    __shared__ float gs[64], bs[64];
    const int tid = threadIdx.x;
    if (tid < 64) { gs[tid] = g[tid]; bs[tid] = bi[tid]; }
    for (int e = tid; e < 576; e += 256) ws[e] = W[e];
    __syncthreads();

    const int b = blockIdx.y;
    const int p = blockIdx.x * 256 + tid;
    const float* xb = x + (size_t)b * 9 * P;
    float xv[9];
#pragma unroll
    for (int c = 0; c < 9; c++) xv[c] = xb[(size_t)c * P + p];
    float* ob = out + (size_t)b * 64 * P;
#pragma unroll 8
    for (int o = 0; o < 64; o++) {
        float a = 0.f;
#pragma unroll
        for (int c = 0; c < 9; c++) a = fmaf(ws[o * 9 + c], xv[c], a);
        ob[(size_t)o * P + p] = fmaxf(fmaf(a, gs[o], bs[o]), 0.f);
    }
}

// ---------------- f32x2 SGEMM: 128o x 128p tile, K-chunk 16, double-buffered -------
#define KC 16
template <int MAXPOOL>
__global__ __launch_bounds__(256, 2) void sgemm_kernel(
    const float* __restrict__ x, const float* __restrict__ Wd,
    const float* __restrict__ g, const float* __restrict__ bi,
    float* __restrict__ out, int Cin, int Cout, int P, int S, int K) {
    __shared__ float ws[2][KC][264];
    __shared__ float xs[2][KC][128];

    const int b = blockIdx.z;
    const int o0 = blockIdx.y * 128;
    const int p0 = blockIdx.x * 128;
    const int tid = threadIdx.x;
    const int w = tid >> 5, l = tid & 31;
    const int warp_o = (w & 3) * 32;
    const int warp_p = (w >> 2) * 64;
    const int ofs = warp_o + ((l >> 3) << 2);
    const int pfs = warp_p + ((l & 7) << 2);

    const float* xb = x + (size_t)b * Cin * P;
    const int twoC = 2 * Cout;

    unsigned long long acc2[8][4];
#pragma unroll
    for (int i = 0; i < 8; i++)
#pragma unroll
        for (int j = 0; j < 4; j++) acc2[i][j] = 0ull;

    const int nch = (Cin + KC - 1) / KC;

    auto stage = [&](int c0, int buf) {
        // ws: KC rows x 256 duplicated words
#pragma unroll
        for (int i = 0; i < 4; i++) {
            int e = tid + i * 256;
            int k = e >> 6, w4 = (e & 63) * 4;
            int cc = c0 + k;
            bool v = cc < Cin;
            const float* src = v ? (Wd + (size_t)cc * twoC + 2 * o0 + w4) : Wd;
            cp16(smem_u32(&ws[buf][k][w4]), src, v);
        }
        // xs: KC rows x 128 words
#pragma unroll
        for (int i = 0; i < 2; i++) {
            int e = tid + i * 256;
            int k = e >> 5, p4 = (e & 31) * 4;
            int cc = c0 + k;
            bool v = (cc < Cin) && (p0 + p4 < P);
            const float* src = v ? (xb + (size_t)cc * P + p0 + p4) : xb;
            cp16(smem_u32(&xs[buf][k][p4]), src, v);
        }
    };

    stage(0, 0);
    cp_commit();

    for (int c = 0; c < nch; c++) {
        if (c + 1 < nch) {
            stage((c + 1) * KC, (c + 1) & 1);
            cp_commit();
            cp_wait<1>();
        } else {
            cp_wait<0>();
        }
        __syncthreads();

        const float(*wsb)[264] = ws[c & 1];
        const float(*xsb)[128] = xs[c & 1];
#pragma unroll
        for (int k = 0; k < KC; k++) {
            ulonglong2 a01 = *(const ulonglong2*)&wsb[k][2 * ofs];
            ulonglong2 a23 = *(const ulonglong2*)&wsb[k][2 * ofs + 4];
            ulonglong2 a45 = *(const ulonglong2*)&wsb[k][2 * (ofs + 16)];
            ulonglong2 a67 = *(const ulonglong2*)&wsb[k][2 * (ofs + 16) + 4];
            ulonglong2 b01 = *(const ulonglong2*)&xsb[k][pfs];
            ulonglong2 b23 = *(const ulonglong2*)&xsb[k][pfs + 32];
            unsigned long long av[8] = {a01.x, a01.y, a23.x, a23.y,
                                        a45.x, a45.y, a67.x, a67.y};
            unsigned long long bv[4] = {b01.x, b01.y, b23.x, b23.y};
#pragma unroll
            for (int i = 0; i < 8; i++)
#pragma unroll
                for (int j = 0; j < 4; j++) fma2(acc2[i][j], av[i], bv[j]);
        }
        __syncthreads();
    }

#pragma unroll
    for (int i = 0; i < 8; i++) {
        int o = o0 + ofs + ((i < 4) ? i : (12 + i));
        float gv = g[o], bb = bi[o];
        float vf[8];
#pragma unroll
        for (int j = 0; j < 4; j++) {
            vf[2 * j]     = fmaxf(fmaf(u64lo(acc2[i][j]), gv, bb), 0.f);
            vf[2 * j + 1] = fmaxf(fmaf(u64hi(acc2[i][j]), gv, bb), 0.f);
        }
        if (MAXPOOL == 0) {
            float* ob = out + (size_t)b * Cout * P + (size_t)o * P;
            if (p0 + pfs < P) {
                float4 v0 = make_float4(vf[0], vf[1], vf[2], vf[3]);
                *(float4*)&ob[p0 + pfs] = v0;
            }
            if (p0 + pfs + 32 < P) {
                float4 v1 = make_float4(vf[4], vf[5], vf[6], vf[7]);
                *(float4*)&ob[p0 + pfs + 32] = v1;
            }
        } else {
            if (K == 64) {
                float m = vf[0];
#pragma unroll
                for (int j = 1; j < 8; j++) m = fmaxf(m, vf[j]);
#pragma unroll
                for (int off = 1; off < 8; off <<= 1)
                    m = fmaxf(m, __shfl_xor_sync(0xffffffffu, m, off));
                if ((l & 7) == 0) {
                    int pg = p0 + warp_p;
                    if (pg < P)
                        out[((size_t)b * Cout + o) * S + (pg >> 6)] = m;
                }
            } else {  // K == 32
                float m0 = fmaxf(fmaxf(vf[0], vf[1]), fmaxf(vf[2], vf[3]));
                float m1 = fmaxf(fmaxf(vf[4], vf[5]), fmaxf(vf[6], vf[7]));
#pragma unroll
                for (int off = 1; off < 8; off <<= 1) {
                    m0 = fmaxf(m0, __shfl_xor_sync(0xffffffffu, m0, off));
                    m1 = fmaxf(m1, __shfl_xor_sync(0xffffffffu, m1, off));
                }
                if ((l & 7) == 0) {
                    int pg = p0 + warp_p;
                    if (pg < P)
                        out[((size_t)b * Cout + o) * S + (pg >> 5)] = m0;
                    if (pg + 32 < P)
                        out[((size_t)b * Cout + o) * S + ((pg + 32) >> 5)] = m1;
                }
            }
        }
    }
}

// ---------------- dense layer on [B, Cin] vectors (classifier head) ----------------
__global__ void dense_kernel(const float* __restrict__ x, const float* __restrict__ W,
                             const float* __restrict__ g, const float* __restrict__ bi,
                             float* __restrict__ out, int Cin, int Cout, int do_relu) {
    const int b = blockIdx.x;
    const int o = blockIdx.y * 8 + (threadIdx.x >> 5);
    const int lane = threadIdx.x & 31;
    if (o >= Cout) return;
    const float* xb = x + (size_t)b * Cin;
    float acc = 0.f;
    for (int c = lane; c < Cin; c += 32)
        acc = fmaf(W[(size_t)o * Cin + c], xb[c], acc);
#pragma unroll
    for (int off = 16; off; off >>= 1)
        acc += __shfl_xor_sync(0xffffffffu, acc, off);
    if (lane == 0) {
        float v = g ? fmaf(acc, g[o], bi[o]) : (acc + bi[o]);
        if (do_relu) v = fmaxf(v, 0.f);
        out[(size_t)b * Cout + o] = v;
    }
}

// ---------------- launch ----------------
extern "C" void kernel_launch(void* const* d_in, const int* in_sizes, int n_in,
                              void* d_out, int out_size) {
    const float* pc = (const float*)d_in[0];
    const float* saw[3][2];
    const float* sag[3][2];
    const float* sab[3][2];
    for (int sm = 0; sm < 3; sm++)
        for (int l = 0; l < 2; l++) {
            int base = 1 + sm * 6 + l * 3;
            saw[sm][l] = (const float*)d_in[base + 0];
            sag[sm][l] = (const float*)d_in[base + 1];
            sab[sm][l] = (const float*)d_in[base + 2];
        }
    const float* clsw[4];
    const float* clsg[3];
    const float* clsb[4];
    for (int l = 0; l < 3; l++) {
        clsw[l] = (const float*)d_in[19 + l * 3 + 0];
        clsg[l] = (const float*)d_in[19 + l * 3 + 1];
        clsb[l] = (const float*)d_in[19 + l * 3 + 2];
    }
    clsw[3] = (const float*)d_in[28];
    clsb[3] = (const float*)d_in[29];

    float *xyz2, *grp1, *h1, *feat2, *xyz3, *grp2, *h2, *feat3;
    float *xyz4, *grp3, *h3, *feat4, *c1, *c2, *c3, *wdup;
    int *sidx1, *sidx2, *sidx3;
    cudaGetSymbolAddress((void**)&sidx1, g_sidx1);
    cudaGetSymbolAddress((void**)&xyz2, g_xyz2);
    cudaGetSymbolAddress((void**)&grp1, g_grp1);
    cudaGetSymbolAddress((void**)&h1, g_h1);
    cudaGetSymbolAddress((void**)&feat2, g_feat2);
    cudaGetSymbolAddress((void**)&sidx2, g_sidx2);
    cudaGetSymbolAddress((void**)&xyz3, g_xyz3);
    cudaGetSymbolAddress((void**)&grp2, g_grp2);
    cudaGetSymbolAddress((void**)&h2, g_h2);
    cudaGetSymbolAddress((void**)&feat3, g_feat3);
    cudaGetSymbolAddress((void**)&sidx3, g_sidx3);
    cudaGetSymbolAddress((void**)&xyz4, g_xyz4);
    cudaGetSymbolAddress((void**)&grp3, g_grp3);
    cudaGetSymbolAddress((void**)&h3, g_h3);
    cudaGetSymbolAddress((void**)&feat4, g_feat4);
    cudaGetSymbolAddress((void**)&c1, g_c1);
    cudaGetSymbolAddress((void**)&c2, g_c2);
    cudaGetSymbolAddress((void**)&c3, g_c3);
    cudaGetSymbolAddress((void**)&wdup, g_wdup);

    // merged weight duplication
    dup_all_kernel<<<(714624 + 255) / 256, 256>>>(saw[0][1], saw[1][0], saw[1][1],
                                                  saw[2][0], saw[2][1], wdup);

    // ---- SA1: N=4096 -> S=512, K=32, r=0.1, C: 9 -> 64 -> 128 ----
    fps_kernel<8><<<BB, 512>>>(pc, 9, NPTS, 512, sidx1);
    bq_group_kernel<<<dim3(512, BB), 256>>>(pc, 9, sidx1, pc + 3,
                                            (size_t)NPTS * 9, 1, 9,
                                            xyz2, grp1, NPTS, 512, 32, 6,
                                            (float)(0.1 * 0.1));
    conv9_kernel<<<dim3(16384 / 256, BB), 256>>>(
        grp1, saw[0][0], sag[0][0], sab[0][0], h1, 16384);
    sgemm_kernel<1><<<dim3(16384 / 128, 1, BB), 256>>>(
        h1, wdup + WD0, sag[0][1], sab[0][1], feat2, 64, 128, 16384, 512, 32);

    // ---- SA2: N=512 -> S=64, K=64, r=0.2, C: 131 -> 128 -> 256 ----
    fps_kernel<1><<<BB, 512>>>(xyz2, 3, 512, 64, sidx2);
    bq_group_kernel<<<dim3(64, BB), 256>>>(xyz2, 3, sidx2, feat2,
                                           (size_t)128 * 512, 512, 1,
                                           xyz3, grp2, 512, 64, 64, 128,
                                           (float)(0.2 * 0.2));
    sgemm_kernel<0><<<dim3(4096 / 128, 1, BB), 256>>>(
        grp2, wdup + WD1, sag[1][0], sab[1][0], h2, 131, 128, 4096, 0, 0);
    sgemm_kernel<1><<<dim3(4096 / 128, 2, BB), 256>>>(
        h2, wdup + WD2, sag[1][1], sab[1][1], feat3, 128, 256, 4096, 64, 64);

    // ---- SA3: N=64 -> S=1, K=64, r=0.4, C: 259 -> 512 -> 1024 ----
    fps_kernel<1><<<BB, 512>>>(xyz3, 3, 64, 1, sidx3);
    bq_group_kernel<<<dim3(1, BB), 256>>>(xyz3, 3, sidx3, feat3,
                                          (size_t)256 * 64, 64, 1,
                                          xyz4, grp3, 64, 1, 64, 256,
                                          (float)(0.4 * 0.4));
    sgemm_kernel<0><<<dim3(1, 4, BB), 256>>>(
        grp3, wdup + WD3, sag[2][0], sab[2][0], h3, 259, 512, 64, 0, 0);
    sgemm_kernel<1><<<dim3(1, 8, BB), 256>>>(
        h3, wdup + WD4, sag[2][1], sab[2][1], feat4, 512, 1024, 64, 1, 64);

    // ---- classifier head on [B, 1024] ----
    dense_kernel<<<dim3(BB, 1024 / 8), 256>>>(feat4, clsw[0], clsg[0], clsb[0], c1, 1024, 1024, 1);
    dense_kernel<<<dim3(BB, 512 / 8), 256>>>(c1, clsw[1], clsg[1], clsb[1], c2, 1024, 512, 1);
    dense_kernel<<<dim3(BB, 128 / 8), 256>>>(c2, clsw[2], clsg[2], clsb[2], c3, 512, 128, 1);
    dense_kernel<<<dim3(BB, (63 + 7) / 8), 256>>>(c3, clsw[3], nullptr, clsb[3],
                                                  (float*)d_out, 128, 63, 0);
}

// round 6
// speedup vs baseline: 1.2865x; 1.2865x over previous
#include <cuda_runtime.h>
#include <cuda_bf16.h>
#include <cstdint>

#define BB 16
#define NPTS 4096

// ---------------- scratch (static device globals; no allocation) ----------------
__device__ __align__(16) float g_xyz1[BB * NPTS * 3];
__device__ __align__(16) float g_feat1[BB * 6 * NPTS];
__device__ __align__(16) int   g_sidx1[BB * 512];
__device__ __align__(16) float g_xyz2[BB * 512 * 3];
__device__ __align__(16) float g_grp1[BB * 9 * 512 * 32];
__device__ __align__(16) float g_h1[BB * 64 * 512 * 32];
__device__ __align__(16) float g_feat2[BB * 128 * 512];
__device__ __align__(16) int   g_sidx2[BB * 64];
__device__ __align__(16) float g_xyz3[BB * 64 * 3];
__device__ __align__(16) float g_grp2[BB * 131 * 64 * 64];
__device__ __align__(16) float g_h2[BB * 128 * 64 * 64];
__device__ __align__(16) float g_feat3[BB * 256 * 64];
__device__ __align__(16) int   g_sidx3[BB * 1];
__device__ __align__(16) float g_xyz4[BB * 3];
__device__ __align__(16) float g_grp3[BB * 259 * 64];
__device__ __align__(16) float g_h3[BB * 512 * 64];
__device__ __align__(16) float g_feat4[BB * 1024];
__device__ __align__(16) float g_c1[BB * 1024];
__device__ __align__(16) float g_c2[BB * 512];
__device__ __align__(16) float g_c3[BB * 128];
// bf16 hi/lo weight planes, [Cout][Cpad] row-major, Cpad = ceil(Cin/16)*16
__device__ __align__(16) __nv_bfloat16 g_wh[722944];
__device__ __align__(16) __nv_bfloat16 g_wl[722944];
// layer offsets into g_wh/g_wl (elements)
#define WO0 0        // SA1-L2: 128 x 64   (Cin 64,  Cpad 64)
#define WO1 8192     // SA2-L1: 128 x 144  (Cin 131, Cpad 144)
#define WO2 26624    // SA2-L2: 256 x 128
#define WO3 59392    // SA3-L1: 512 x 272  (Cin 259, Cpad 272)
#define WO4 198656   // SA3-L2: 1024 x 512

// ---------------- helpers ----------------
__device__ __forceinline__ uint32_t smem_u32(const void* p) {
    return (uint32_t)__cvta_generic_to_shared(p);
}
__device__ __forceinline__ void cp16(uint32_t dst, const void* src) {
    asm volatile("cp.async.ca.shared.global [%0], [%1], 16;" :: "r"(dst), "l"(src));
}
__device__ __forceinline__ void cp_commit() {
    asm volatile("cp.async.commit_group;");
}
template <int N>
__device__ __forceinline__ void cp_wait() {
    asm volatile("cp.async.wait_group %0;" :: "n"(N));
}
__device__ __forceinline__ void mma16816(float* c, const uint32_t* a, const uint32_t* b) {
    asm("mma.sync.aligned.m16n8k16.row.col.f32.bf16.bf16.f32 "
        "{%0,%1,%2,%3},{%4,%5,%6,%7},{%8,%9},{%0,%1,%2,%3};"
        : "+f"(c[0]), "+f"(c[1]), "+f"(c[2]), "+f"(c[3])
        : "r"(a[0]), "r"(a[1]), "r"(a[2]), "r"(a[3]), "r"(b[0]), "r"(b[1]));
}

// ---------------- weight prep: f32 -> bf16 hi/lo planes, padded ----------------
__global__ void prep_w_kernel(const float* __restrict__ w0, const float* __restrict__ w1,
                              const float* __restrict__ w2, const float* __restrict__ w3,
                              const float* __restrict__ w4) {
    int i = blockIdx.x * 256 + threadIdx.x;
    const float* W;
    int Cin, Cpad;
    size_t off;
    if (i < 8192)        { W = w0; Cin = 64;  Cpad = 64;  off = WO0; }
    else if (i < 26624)  { W = w1; Cin = 131; Cpad = 144; off = WO1; i -= 8192; }
    else if (i < 59392)  { W = w2; Cin = 128; Cpad = 128; off = WO2; i -= 26624; }
    else if (i < 198656) { W = w3; Cin = 259; Cpad = 272; off = WO3; i -= 59392; }
    else if (i < 722944) { W = w4; Cin = 512; Cpad = 512; off = WO4; i -= 198656; }
    else return;
    int o = i / Cpad, c = i - o * Cpad;
    float v = (c < Cin) ? W[(size_t)o * Cin + c] : 0.f;
    __nv_bfloat16 h = __float2bfloat16(v);
    float lo = v - __bfloat162float(h);
    g_wh[off + i] = h;
    g_wl[off + i] = __float2bfloat16(lo);
}

// ---------------- split pointcloud ----------------
__global__ void split_kernel(const float* __restrict__ pc,
                             float* __restrict__ xyz, float* __restrict__ feat) {
    int idx = blockIdx.x * blockDim.x + threadIdx.x;
    if (idx >= BB * NPTS) return;
    int b = idx / NPTS, n = idx % NPTS;
    const float* p = pc + (size_t)idx * 9;
    xyz[idx * 3 + 0] = p[0];
    xyz[idx * 3 + 1] = p[1];
    xyz[idx * 3 + 2] = p[2];
#pragma unroll
    for (int c = 0; c < 6; c++)
        feat[((size_t)b * 6 + c) * NPTS + n] = p[3 + c];
}

// ---------------- FPS (round-3 proven version: 1024 thr, two-level REDUX) ----------
__global__ void fps_kernel(const float* __restrict__ xyz, int N, int npoint,
                           int* __restrict__ out) {
    const int b = blockIdx.x;
    const float* px = xyz + (size_t)b * N * 3;
    const int tid = threadIdx.x;
    const int ITEMS = 4;

    float lx[ITEMS], ly[ITEMS], lz[ITEMS], ld[ITEMS];
#pragma unroll
    for (int i = 0; i < ITEMS; i++) {
        int n = tid + i * 1024;
        if (n < N) {
            lx[i] = px[n * 3 + 0];
            ly[i] = px[n * 3 + 1];
            lz[i] = px[n * 3 + 2];
            ld[i] = 1e10f;
        } else {
            ld[i] = -1.0f;
        }
    }

    __shared__ int s_far;
    __shared__ unsigned sv[32];
    __shared__ unsigned si[32];
    if (tid == 0) s_far = 0;
    __syncthreads();

    for (int it = 0; it < npoint; it++) {
        int far = s_far;
        if (tid == 0) out[b * npoint + it] = far;
        float cx = px[far * 3 + 0];
        float cy = px[far * 3 + 1];
        float cz = px[far * 3 + 2];

        float bv = -1.0f;
        int bi = 0;
#pragma unroll
        for (int i = 0; i < ITEMS; i++) {
            int n = tid + i * 1024;
            if (n < N) {
                float dx = __fsub_rn(lx[i], cx);
                float dy = __fsub_rn(ly[i], cy);
                float dz = __fsub_rn(lz[i], cz);
                float d = __fadd_rn(__fadd_rn(__fmul_rn(dx, dx), __fmul_rn(dy, dy)),
                                    __fmul_rn(dz, dz));
                float nd = fminf(ld[i], d);
                ld[i] = nd;
                if (nd > bv) { bv = nd; bi = n; }
            }
        }
        unsigned ub = (tid < N) ? __float_as_uint(bv) : 0u;
        unsigned wmax = __reduce_max_sync(0xffffffffu, ub);
        unsigned uidx = (tid < N && ub == wmax) ? (unsigned)bi : 0xffffffffu;
        unsigned wimin = __reduce_min_sync(0xffffffffu, uidx);
        if ((tid & 31) == 0) { sv[tid >> 5] = wmax; si[tid >> 5] = wimin; }
        __syncthreads();
        if (tid < 32) {
            unsigned v2 = sv[tid], i2 = si[tid];
            unsigned m2 = __reduce_max_sync(0xffffffffu, v2);
            unsigned ii = (v2 == m2) ? i2 : 0xffffffffu;
            unsigned fi = __reduce_min_sync(0xffffffffu, ii);
            if (tid == 0) s_far = (int)fi;
        }
        __syncthreads();
    }
}

// ---------------- ball query + gather/group (round-3 proven) ----------------
__global__ void bq_group_kernel(const float* __restrict__ xyz, const int* __restrict__ sidx,
                                const float* __restrict__ feats,
                                float* __restrict__ new_xyz, float* __restrict__ grp,
                                int N, int S, int K, int Cf, float r2) {
    const int b = blockIdx.y, s = blockIdx.x;
    const float* px = xyz + (size_t)b * N * 3;
    const int ci = sidx[b * S + s];
    const float cx = px[ci * 3 + 0];
    const float cy = px[ci * 3 + 1];
    const float cz = px[ci * 3 + 2];
    const int tid = threadIdx.x;

    __shared__ int sIdx[64];

    if (tid == 0) {
        new_xyz[((size_t)b * S + s) * 3 + 0] = cx;
        new_xyz[((size_t)b * S + s) * 3 + 1] = cy;
        new_xyz[((size_t)b * S + s) * 3 + 2] = cz;
    }

    if (tid < 32) {
        int cnt = 0, first = -1;
        for (int base = 0; base < N; base += 32) {
            int j = base + tid;
            bool pred = false;
            if (j < N) {
                float dx = __fsub_rn(cx, px[j * 3 + 0]);
                float dy = __fsub_rn(cy, px[j * 3 + 1]);
                float dz = __fsub_rn(cz, px[j * 3 + 2]);
                float d2 = __fadd_rn(__fadd_rn(__fmul_rn(dx, dx), __fmul_rn(dy, dy)),
                                     __fmul_rn(dz, dz));
                pred = (d2 < r2);
            }
            unsigned m = __ballot_sync(0xffffffffu, pred);
            if (first < 0 && m) first = base + __ffs(m) - 1;
            if (pred) {
                int pos = cnt + __popc(m & ((1u << tid) - 1u));
                if (pos < K) sIdx[pos] = j;
            }
            cnt += __popc(m);
            if (cnt >= K) break;
        }
        int fillv = (first < 0) ? 0 : first;
        for (int k = cnt + tid; k < K; k += 32) sIdx[k] = fillv;
    }
    __syncthreads();

    const int C = 3 + Cf;
    const size_t SK = (size_t)S * K;
    const size_t pbase = (size_t)s * K;
    for (int e = tid; e < C * K; e += blockDim.x) {
        int ch = e / K, k = e - ch * K;
        int j = sIdx[k];
        float v;
        if (ch == 0)      v = __fsub_rn(px[j * 3 + 0], cx);
        else if (ch == 1) v = __fsub_rn(px[j * 3 + 1], cy);
        else if (ch == 2) v = __fsub_rn(px[j * 3 + 2], cz);
        else              v = feats[((size_t)b * Cf + (ch - 3)) * N + j];
        grp[((size_t)b * C + ch) * SK + pbase + k] = v;
    }
}

// ---------------- SA1 layer1: 9 -> 64 streaming conv + BN + ReLU ----------------
__global__ void conv9_kernel(const float* __restrict__ x, const float* __restrict__ W,
                             const float* __restrict__ g, const float* __restrict__ bi,
                             float* __restrict__ out, int P) {
    __shared__ float ws[64 * 9];
    __shared__ float gs[64], bs[64];
    const int tid = threadIdx.x;
    if (tid < 64) { gs[tid] = g[tid]; bs[tid] = bi[tid]; }
    for (int e = tid; e < 576; e += 256) ws[e] = W[e];
    __syncthreads();

    const int b = blockIdx.y;
    const int p = blockIdx.x * 256 + tid;
    const float* xb = x + (size_t)b * 9 * P;
    float xv[9];
#pragma unroll
    for (int c = 0; c < 9; c++) xv[c] = xb[(size_t)c * P + p];
    float* ob = out + (size_t)b * 64 * P;
#pragma unroll 8
    for (int o = 0; o < 64; o++) {
        float a = 0.f;
#pragma unroll
        for (int c = 0; c < 9; c++) a = fmaf(ws[o * 9 + c], xv[c], a);
        ob[(size_t)o * P + p] = fmaxf(fmaf(a, gs[o], bs[o]), 0.f);
    }
}

// ---------------- bf16 split-MMA GEMM: 64o x 128p block tile, K-chunk 16 -----------
// C[o][p] = sum_c W[o][c] X[c][p], computed as Wh*Xh + Wh*Xl + Wl*Xh (3 MMAs).
// MAXPOOL=0: out[b][o][p] = relu(g*acc+b).  MAXPOOL=1: out[b][o][s] = max_K relu(...).
// 8 warps = 2(M) x 4(N); warp tile 32o x 32p = 2x4 m16n8 frags.
template <int MAXPOOL>
__global__ __launch_bounds__(256, 2) void mma_gemm_kernel(
    const float* __restrict__ x, const __nv_bfloat16* __restrict__ Wh,
    const __nv_bfloat16* __restrict__ Wl, const float* __restrict__ g,
    const float* __restrict__ bi, float* __restrict__ out,
    int Cin, int Cpad, int Cout, int P, int S, int K) {
    __shared__ uint32_t sWh[2][64][12], sWl[2][64][12];  // [o][c-pair], pitch 12
    __shared__ uint32_t sXh[128][12], sXl[128][12];      // [p][c-pair]
    __shared__ float red[4][64];

    const int b = blockIdx.z;
    const int o0 = blockIdx.y * 64;
    const int p0 = blockIdx.x * 128;
    const int tid = threadIdx.x;
    const int w = tid >> 5, l = tid & 31;
    const int gq = l >> 2, tq = l & 3;
    const int wm = w & 1, wn = w >> 1;

    const float* xb = x + (size_t)b * Cin * P;
    const int nch = (Cin + 15) >> 4;

    float acc[2][4][4];
#pragma unroll
    for (int i = 0; i < 2; i++)
#pragma unroll
        for (int j = 0; j < 4; j++)
#pragma unroll
            for (int r = 0; r < 4; r++) acc[i][j][r] = 0.f;

    // W stage via cp.async: which(hi/lo) = tid&1, row r, half(0/1) 16B each
    auto stage_w = [&](int c0, int buf) {
        int which = tid & 1, r = (tid >> 1) & 63, half = (tid >> 7) & 1;
        const __nv_bfloat16* src =
            (which ? Wl : Wh) + (size_t)(o0 + r) * Cpad + c0 + half * 8;
        uint32_t dst = smem_u32(which ? &sWl[buf][r][half * 4] : &sWh[buf][r][half * 4]);
        cp16(dst, src);
    };
    // X prefetch to regs: thread owns p = tid&127, 8 consecutive c's
    const int xp = tid & 127;
    const int xch = (tid >> 7) * 8;
    auto load_x = [&](int c0, float xr[8]) {
        bool pv = (p0 + xp) < P;
#pragma unroll
        for (int q = 0; q < 8; q++) {
            int cc = c0 + xch + q;
            xr[q] = (pv && cc < Cin) ? xb[(size_t)cc * P + p0 + xp] : 0.f;
        }
    };
    auto store_x = [&](const float xr[8]) {
        uint32_t hq[4], lq[4];
#pragma unroll
        for (int k = 0; k < 4; k++) {
            float a = xr[2 * k], c = xr[2 * k + 1];
            __nv_bfloat16 ah = __float2bfloat16(a), ch = __float2bfloat16(c);
            float al = a - __bfloat162float(ah), cl = c - __bfloat162float(ch);
            hq[k] = (uint32_t)__bfloat16_as_ushort(ah) |
                    ((uint32_t)__bfloat16_as_ushort(ch) << 16);
            lq[k] = (uint32_t)__bfloat16_as_ushort(__float2bfloat16(al)) |
                    ((uint32_t)__bfloat16_as_ushort(__float2bfloat16(cl)) << 16);
        }
        *(uint4*)&sXh[xp][(xch >> 1)] = make_uint4(hq[0], hq[1], hq[2], hq[3]);
        *(uint4*)&sXl[xp][(xch >> 1)] = make_uint4(lq[0], lq[1], lq[2], lq[3]);
    };

    float xr[8], xr2[8];
    load_x(0, xr);
    stage_w(0, 0);
    cp_commit();

    for (int c = 0; c < nch; c++) {
        __syncthreads();  // previous mma done reading sX
        store_x(xr);
        if (c + 1 < nch) {
            load_x((c + 1) * 16, xr2);
            stage_w((c + 1) * 16, (c + 1) & 1);
            cp_commit();
            cp_wait<1>();
        } else {
            cp_wait<0>();
        }
        __syncthreads();  // sX stores + W chunk c visible

        const uint32_t(*wh)[12] = sWh[c & 1];
        const uint32_t(*wl)[12] = sWl[c & 1];
        uint32_t ah[2][4], al[2][4], bh[4][2], bl[4][2];
#pragma unroll
        for (int i = 0; i < 2; i++) {
            int ro = wm * 32 + i * 16;
            ah[i][0] = wh[ro + gq][tq];
            ah[i][1] = wh[ro + gq + 8][tq];
            ah[i][2] = wh[ro + gq][tq + 4];
            ah[i][3] = wh[ro + gq + 8][tq + 4];
            al[i][0] = wl[ro + gq][tq];
            al[i][1] = wl[ro + gq + 8][tq];
            al[i][2] = wl[ro + gq][tq + 4];
            al[i][3] = wl[ro + gq + 8][tq + 4];
        }
#pragma unroll
        for (int j = 0; j < 4; j++) {
            int rp = wn * 32 + j * 8 + gq;
            bh[j][0] = sXh[rp][tq];
            bh[j][1] = sXh[rp][tq + 4];
            bl[j][0] = sXl[rp][tq];
            bl[j][1] = sXl[rp][tq + 4];
        }
#pragma unroll
        for (int i = 0; i < 2; i++)
#pragma unroll
            for (int j = 0; j < 4; j++) {
                mma16816(acc[i][j], ah[i], bh[j]);
                mma16816(acc[i][j], ah[i], bl[j]);
                mma16816(acc[i][j], al[i], bh[j]);
            }
        if (c + 1 < nch) {
#pragma unroll
            for (int q = 0; q < 8; q++) xr[q] = xr2[q];
        }
    }

    // ---- epilogue ----
#pragma unroll
    for (int i = 0; i < 2; i++) {
#pragma unroll
        for (int half = 0; half < 2; half++) {
            int orow = o0 + wm * 32 + i * 16 + gq + half * 8;
            float gv = g[orow], bv = bi[orow];
            if (MAXPOOL == 0) {
                float* ob = out + (size_t)b * Cout * P + (size_t)orow * P;
#pragma unroll
                for (int j = 0; j < 4; j++) {
                    int pb = p0 + wn * 32 + j * 8 + 2 * tq;
                    float v0 = fmaxf(fmaf(acc[i][j][half * 2], gv, bv), 0.f);
                    float v1 = fmaxf(fmaf(acc[i][j][half * 2 + 1], gv, bv), 0.f);
                    if (pb < P) ob[pb] = v0;
                    if (pb + 1 < P) ob[pb + 1] = v1;
                }
            } else {
                float m = 0.f;  // relu values are >= 0
#pragma unroll
                for (int j = 0; j < 4; j++) {
                    m = fmaxf(m, fmaxf(fmaf(acc[i][j][half * 2], gv, bv),
                                       fmaf(acc[i][j][half * 2 + 1], gv, bv)));
                }
                m = fmaxf(m, 0.f);
                m = fmaxf(m, __shfl_xor_sync(0xffffffffu, m, 1));
                m = fmaxf(m, __shfl_xor_sync(0xffffffffu, m, 2));
                if (tq == 0) red[wn][wm * 32 + i * 16 + half * 8 + gq] = m;
            }
        }
    }
    if (MAXPOOL == 1) {
        __syncthreads();
        if (K == 32) {
            int o = tid & 63, grp = tid >> 6;
            if (p0 + grp * 32 < P)
                out[((size_t)b * Cout + o0 + o) * S + (p0 >> 5) + grp] = red[grp][o];
        } else {  // K == 64
            if (tid < 128) {
                int o = tid & 63, grp = tid >> 6;
                if (p0 + grp * 64 < P) {
                    float m = fmaxf(red[2 * grp][o], red[2 * grp + 1][o]);
                    out[((size_t)b * Cout + o0 + o) * S + (p0 >> 6) + grp] = m;
                }
            }
        }
    }
}

// ---------------- dense layer on [B, Cin] vectors (classifier head) ----------------
__global__ void dense_kernel(const float* __restrict__ x, const float* __restrict__ W,
                             const float* __restrict__ g, const float* __restrict__ bi,
                             float* __restrict__ out, int Cin, int Cout, int do_relu) {
    const int b = blockIdx.x;
    const int o = blockIdx.y * 8 + (threadIdx.x >> 5);
    const int lane = threadIdx.x & 31;
    if (o >= Cout) return;
    const float* xb = x + (size_t)b * Cin;
    float acc = 0.f;
    for (int c = lane; c < Cin; c += 32)
        acc = fmaf(W[(size_t)o * Cin + c], xb[c], acc);
#pragma unroll
    for (int off = 16; off; off >>= 1)
        acc += __shfl_xor_sync(0xffffffffu, acc, off);
    if (lane == 0) {
        float v = g ? fmaf(acc, g[o], bi[o]) : (acc + bi[o]);
        if (do_relu) v = fmaxf(v, 0.f);
        out[(size_t)b * Cout + o] = v;
    }
}

// ---------------- launch ----------------
extern "C" void kernel_launch(void* const* d_in, const int* in_sizes, int n_in,
                              void* d_out, int out_size) {
    const float* pc = (const float*)d_in[0];
    const float* saw[3][2];
    const float* sag[3][2];
    const float* sab[3][2];
    for (int sm = 0; sm < 3; sm++)
        for (int l = 0; l < 2; l++) {
            int base = 1 + sm * 6 + l * 3;
            saw[sm][l] = (const float*)d_in[base + 0];
            sag[sm][l] = (const float*)d_in[base + 1];
            sab[sm][l] = (const float*)d_in[base + 2];
        }
    const float* clsw[4];
    const float* clsg[3];
    const float* clsb[4];
    for (int l = 0; l < 3; l++) {
        clsw[l] = (const float*)d_in[19 + l * 3 + 0];
        clsg[l] = (const float*)d_in[19 + l * 3 + 1];
        clsb[l] = (const float*)d_in[19 + l * 3 + 2];
    }
    clsw[3] = (const float*)d_in[28];
    clsb[3] = (const float*)d_in[29];

    float *xyz1, *feat1, *xyz2, *grp1, *h1, *feat2, *xyz3, *grp2, *h2, *feat3;
    float *xyz4, *grp3, *h3, *feat4, *c1, *c2, *c3;
    int *sidx1, *sidx2, *sidx3;
    __nv_bfloat16 *wh, *wl;
    cudaGetSymbolAddress((void**)&xyz1, g_xyz1);
    cudaGetSymbolAddress((void**)&feat1, g_feat1);
    cudaGetSymbolAddress((void**)&sidx1, g_sidx1);
    cudaGetSymbolAddress((void**)&xyz2, g_xyz2);
    cudaGetSymbolAddress((void**)&grp1, g_grp1);
    cudaGetSymbolAddress((void**)&h1, g_h1);
    cudaGetSymbolAddress((void**)&feat2, g_feat2);
    cudaGetSymbolAddress((void**)&sidx2, g_sidx2);
    cudaGetSymbolAddress((void**)&xyz3, g_xyz3);
    cudaGetSymbolAddress((void**)&grp2, g_grp2);
    cudaGetSymbolAddress((void**)&h2, g_h2);
    cudaGetSymbolAddress((void**)&feat3, g_feat3);
    cudaGetSymbolAddress((void**)&sidx3, g_sidx3);
    cudaGetSymbolAddress((void**)&xyz4, g_xyz4);
    cudaGetSymbolAddress((void**)&grp3, g_grp3);
    cudaGetSymbolAddress((void**)&h3, g_h3);
    cudaGetSymbolAddress((void**)&feat4, g_feat4);
    cudaGetSymbolAddress((void**)&c1, g_c1);
    cudaGetSymbolAddress((void**)&c2, g_c2);
    cudaGetSymbolAddress((void**)&c3, g_c3);
    cudaGetSymbolAddress((void**)&wh, g_wh);
    cudaGetSymbolAddress((void**)&wl, g_wl);

    // weight prep (bf16 hi/lo planes)
    prep_w_kernel<<<(722944 + 255) / 256, 256>>>(saw[0][1], saw[1][0], saw[1][1],
                                                 saw[2][0], saw[2][1]);
    // split
    split_kernel<<<(BB * NPTS + 255) / 256, 256>>>(pc, xyz1, feat1);

    // ---- SA1: N=4096 -> S=512, K=32, r=0.1, C: 9 -> 64 -> 128 ----
    fps_kernel<<<BB, 1024>>>(xyz1, NPTS, 512, sidx1);
    bq_group_kernel<<<dim3(512, BB), 256>>>(xyz1, sidx1, feat1, xyz2, grp1,
                                            NPTS, 512, 32, 6, (float)(0.1 * 0.1));
    conv9_kernel<<<dim3(16384 / 256, BB), 256>>>(
        grp1, saw[0][0], sag[0][0], sab[0][0], h1, 16384);
    mma_gemm_kernel<1><<<dim3(16384 / 128, 2, BB), 256>>>(
        h1, wh + WO0, wl + WO0, sag[0][1], sab[0][1], feat2,
        64, 64, 128, 16384, 512, 32);

    // ---- SA2: N=512 -> S=64, K=64, r=0.2, C: 131 -> 128 -> 256 ----
    fps_kernel<<<BB, 1024>>>(xyz2, 512, 64, sidx2);
    bq_group_kernel<<<dim3(64, BB), 256>>>(xyz2, sidx2, feat2, xyz3, grp2,
                                           512, 64, 64, 128, (float)(0.2 * 0.2));
    mma_gemm_kernel<0><<<dim3(4096 / 128, 2, BB), 256>>>(
        grp2, wh + WO1, wl + WO1, sag[1][0], sab[1][0], h2,
        131, 144, 128, 4096, 1, 1);
    mma_gemm_kernel<1><<<dim3(4096 / 128, 4, BB), 256>>>(
        h2, wh + WO2, wl + WO2, sag[1][1], sab[1][1], feat3,
        128, 128, 256, 4096, 64, 64);

    // ---- SA3: N=64 -> S=1, K=64, r=0.4, C: 259 -> 512 -> 1024 ----
    fps_kernel<<<BB, 1024>>>(xyz3, 64, 1, sidx3);
    bq_group_kernel<<<dim3(1, BB), 256>>>(xyz3, sidx3, feat3, xyz4, grp3,
                                          64, 1, 64, 256, (float)(0.4 * 0.4));
    mma_gemm_kernel<0><<<dim3(1, 8, BB), 256>>>(
        grp3, wh + WO3, wl + WO3, sag[2][0], sab[2][0], h3,
        259, 272, 512, 64, 1, 1);
    mma_gemm_kernel<1><<<dim3(1, 16, BB), 256>>>(
        h3, wh + WO4, wl + WO4, sag[2][1], sab[2][1], feat4,
        512, 512, 1024, 64, 1, 64);

    // ---- classifier head on [B, 1024] ----
    dense_kernel<<<dim3(BB, 1024 / 8), 256>>>(feat4, clsw[0], clsg[0], clsb[0], c1, 1024, 1024, 1);
    dense_kernel<<<dim3(BB, 512 / 8), 256>>>(c1, clsw[1], clsg[1], clsb[1], c2, 1024, 512, 1);
    dense_kernel<<<dim3(BB, 128 / 8), 256>>>(c2, clsw[2], clsg[2], clsb[2], c3, 512, 128, 1);
    dense_kernel<<<dim3(BB, (63 + 7) / 8), 256>>>(c3, clsw[3], nullptr, clsb[3],
                                                  (float*)d_out, 128, 63, 0);
}

// round 7
// speedup vs baseline: 1.6263x; 1.2641x over previous
#include <cuda_runtime.h>
#include <cuda_bf16.h>
#include <cstdint>

#define BB 16
#define NPTS 4096

// ---------------- scratch (static device globals; no allocation) ----------------
__device__ __align__(16) float g_xyz1[BB * NPTS * 3];
__device__ __align__(16) float g_feat1[BB * 6 * NPTS];
__device__ __align__(16) int   g_sidx1[BB * 512];
__device__ __align__(16) float g_xyz2[BB * 512 * 3];
__device__ __align__(16) float g_grp1[BB * 9 * 512 * 32];
__device__ __align__(16) float g_h1[BB * 64 * 512 * 32];
__device__ __align__(16) float g_feat2[BB * 128 * 512];
__device__ __align__(16) int   g_sidx2[BB * 64];
__device__ __align__(16) float g_xyz3[BB * 64 * 3];
__device__ __align__(16) float g_grp2[BB * 131 * 64 * 64];
__device__ __align__(16) float g_h2[BB * 128 * 64 * 64];
__device__ __align__(16) float g_feat3[BB * 256 * 64];
__device__ __align__(16) int   g_sidx3[BB * 1];
__device__ __align__(16) float g_xyz4[BB * 3];
__device__ __align__(16) float g_grp3[BB * 259 * 64];
__device__ __align__(16) float g_h3[BB * 512 * 64];
__device__ __align__(16) float g_feat4[BB * 1024];
__device__ __align__(16) float g_c1[BB * 1024];
__device__ __align__(16) float g_c2[BB * 512];
__device__ __align__(16) float g_c3[BB * 128];
// bf16 hi/lo weight planes, [Cout][Cpad] row-major, Cpad = ceil(Cin/16)*16
__device__ __align__(16) __nv_bfloat16 g_wh[722944];
__device__ __align__(16) __nv_bfloat16 g_wl[722944];
#define WO0 0        // SA1-L2: 128 x 64
#define WO1 8192     // SA2-L1: 128 x 144
#define WO2 26624    // SA2-L2: 256 x 128
#define WO3 59392    // SA3-L1: 512 x 272
#define WO4 198656   // SA3-L2: 1024 x 512

// ---------------- helpers ----------------
__device__ __forceinline__ uint32_t smem_u32(const void* p) {
    return (uint32_t)__cvta_generic_to_shared(p);
}
__device__ __forceinline__ void cp16(uint32_t dst, const void* src) {
    asm volatile("cp.async.ca.shared.global [%0], [%1], 16;" :: "r"(dst), "l"(src));
}
__device__ __forceinline__ void cp_commit() {
    asm volatile("cp.async.commit_group;");
}
template <int N>
__device__ __forceinline__ void cp_wait() {
    asm volatile("cp.async.wait_group %0;" :: "n"(N));
}
__device__ __forceinline__ void mma16816(float* c, const uint32_t* a, const uint32_t* b) {
    asm("mma.sync.aligned.m16n8k16.row.col.f32.bf16.bf16.f32 "
        "{%0,%1,%2,%3},{%4,%5,%6,%7},{%8,%9},{%0,%1,%2,%3};"
        : "+f"(c[0]), "+f"(c[1]), "+f"(c[2]), "+f"(c[3])
        : "r"(a[0]), "r"(a[1]), "r"(a[2]), "r"(a[3]), "r"(b[0]), "r"(b[1]));
}

// ---------------- weight prep: f32 -> bf16 hi/lo planes, padded ----------------
__global__ void prep_w_kernel(const float* __restrict__ w0, const float* __restrict__ w1,
                              const float* __restrict__ w2, const float* __restrict__ w3,
                              const float* __restrict__ w4) {
    int i = blockIdx.x * 256 + threadIdx.x;
    const float* W;
    int Cin, Cpad;
    size_t off;
    if (i < 8192)        { W = w0; Cin = 64;  Cpad = 64;  off = WO0; }
    else if (i < 26624)  { W = w1; Cin = 131; Cpad = 144; off = WO1; i -= 8192; }
    else if (i < 59392)  { W = w2; Cin = 128; Cpad = 128; off = WO2; i -= 26624; }
    else if (i < 198656) { W = w3; Cin = 259; Cpad = 272; off = WO3; i -= 59392; }
    else if (i < 722944) { W = w4; Cin = 512; Cpad = 512; off = WO4; i -= 198656; }
    else return;
    int o = i / Cpad, c = i - o * Cpad;
    float v = (c < Cin) ? W[(size_t)o * Cin + c] : 0.f;
    __nv_bfloat16 h = __float2bfloat16(v);
    float lo = v - __bfloat162float(h);
    g_wh[off + i] = h;
    g_wl[off + i] = __float2bfloat16(lo);
}

// ---------------- split pointcloud ----------------
__global__ void split_kernel(const float* __restrict__ pc,
                             float* __restrict__ xyz, float* __restrict__ feat) {
    int idx = blockIdx.x * blockDim.x + threadIdx.x;
    if (idx >= BB * NPTS) return;
    int b = idx / NPTS, n = idx % NPTS;
    const float* p = pc + (size_t)idx * 9;
    xyz[idx * 3 + 0] = p[0];
    xyz[idx * 3 + 1] = p[1];
    xyz[idx * 3 + 2] = p[2];
#pragma unroll
    for (int c = 0; c < 6; c++)
        feat[((size_t)b * 6 + c) * NPTS + n] = p[3 + c];
}

// ---------------- FPS (1024 thr, two-level REDUX; exact JAX arithmetic) ----------
__global__ void fps_kernel(const float* __restrict__ xyz, int N, int npoint,
                           int* __restrict__ out) {
    const int b = blockIdx.x;
    const float* px = xyz + (size_t)b * N * 3;
    const int tid = threadIdx.x;
    const int ITEMS = 4;

    float lx[ITEMS], ly[ITEMS], lz[ITEMS], ld[ITEMS];
#pragma unroll
    for (int i = 0; i < ITEMS; i++) {
        int n = tid + i * 1024;
        if (n < N) {
            lx[i] = px[n * 3 + 0];
            ly[i] = px[n * 3 + 1];
            lz[i] = px[n * 3 + 2];
            ld[i] = 1e10f;
        } else {
            ld[i] = -1.0f;
        }
    }

    __shared__ int s_far;
    __shared__ unsigned sv[32];
    __shared__ unsigned si[32];
    if (tid == 0) s_far = 0;
    __syncthreads();

    for (int it = 0; it < npoint; it++) {
        int far = s_far;
        if (tid == 0) out[b * npoint + it] = far;
        float cx = px[far * 3 + 0];
        float cy = px[far * 3 + 1];
        float cz = px[far * 3 + 2];

        float bv = -1.0f;
        int bi = 0;
#pragma unroll
        for (int i = 0; i < ITEMS; i++) {
            int n = tid + i * 1024;
            if (n < N) {
                float dx = __fsub_rn(lx[i], cx);
                float dy = __fsub_rn(ly[i], cy);
                float dz = __fsub_rn(lz[i], cz);
                float d = __fadd_rn(__fadd_rn(__fmul_rn(dx, dx), __fmul_rn(dy, dy)),
                                    __fmul_rn(dz, dz));
                float nd = fminf(ld[i], d);
                ld[i] = nd;
                if (nd > bv) { bv = nd; bi = n; }
            }
        }
        unsigned ub = (tid < N) ? __float_as_uint(bv) : 0u;
        unsigned wmax = __reduce_max_sync(0xffffffffu, ub);
        unsigned uidx = (tid < N && ub == wmax) ? (unsigned)bi : 0xffffffffu;
        unsigned wimin = __reduce_min_sync(0xffffffffu, uidx);
        if ((tid & 31) == 0) { sv[tid >> 5] = wmax; si[tid >> 5] = wimin; }
        __syncthreads();
        if (tid < 32) {
            unsigned v2 = sv[tid], i2 = si[tid];
            unsigned m2 = __reduce_max_sync(0xffffffffu, v2);
            unsigned ii = (v2 == m2) ? i2 : 0xffffffffu;
            unsigned fi = __reduce_min_sync(0xffffffffu, ii);
            if (tid == 0) s_far = (int)fi;
        }
        __syncthreads();
    }
}

// ---------------- ball query + gather/group: block-parallel scan ----------------
// Phase A: 8 warps ballot all N points in parallel (masks per 32-pt group in smem).
// Phase B: warp 0 prefix-sums group popcounts -> per-group exclusive base + total.
// Phase C: all warps extract indices with global rank < K; pad with rank-0 hit or 0.
// Semantics identical to JAX first-K-in-index-order with pad-by-first.
__global__ void bq_group_kernel(const float* __restrict__ xyz, const int* __restrict__ sidx,
                                const float* __restrict__ feats,
                                float* __restrict__ new_xyz, float* __restrict__ grp,
                                int N, int S, int K, int Cf, float r2) {
    const int b = blockIdx.y, s = blockIdx.x;
    const float* px = xyz + (size_t)b * N * 3;
    const int ci = sidx[b * S + s];
    const float cx = px[ci * 3 + 0];
    const float cy = px[ci * 3 + 1];
    const float cz = px[ci * 3 + 2];
    const int tid = threadIdx.x;
    const int w = tid >> 5, l = tid & 31;

    __shared__ unsigned smask[128];   // N <= 4096
    __shared__ int sbase[128];
    __shared__ int s_total;
    __shared__ int sIdx[64];

    const int NG = (N + 31) >> 5;     // 32-pt groups
    const int gpw = (NG + 7) >> 3;    // groups per warp (8 warps)

    if (tid == 0) {
        new_xyz[((size_t)b * S + s) * 3 + 0] = cx;
        new_xyz[((size_t)b * S + s) * 3 + 1] = cy;
        new_xyz[((size_t)b * S + s) * 3 + 2] = cz;
    }

    // Phase A: parallel ballot
    for (int gi = 0; gi < gpw; gi++) {
        int g = w * gpw + gi;
        if (g < NG) {
            int j = (g << 5) + l;
            bool pred = false;
            if (j < N) {
                float dx = __fsub_rn(cx, px[j * 3 + 0]);
                float dy = __fsub_rn(cy, px[j * 3 + 1]);
                float dz = __fsub_rn(cz, px[j * 3 + 2]);
                float d2 = __fadd_rn(__fadd_rn(__fmul_rn(dx, dx), __fmul_rn(dy, dy)),
                                     __fmul_rn(dz, dz));
                pred = (d2 < r2);
            }
            unsigned m = __ballot_sync(0xffffffffu, pred);
            if (l == 0) smask[g] = m;
        }
    }
    __syncthreads();

    // Phase B: warp 0 exclusive prefix over group counts
    if (w == 0) {
        const int gpl = (NG + 31) >> 5;  // groups per lane
        int cnt = 0;
#pragma unroll 4
        for (int q = 0; q < gpl; q++) {
            int g = l * gpl + q;
            if (g < NG) cnt += __popc(smask[g]);
        }
        int inc = cnt;
#pragma unroll
        for (int off = 1; off < 32; off <<= 1) {
            int v = __shfl_up_sync(0xffffffffu, inc, off);
            if (l >= off) inc += v;
        }
        int total = __shfl_sync(0xffffffffu, inc, 31);
        int run = inc - cnt;  // exclusive base for this lane's first group
#pragma unroll 4
        for (int q = 0; q < gpl; q++) {
            int g = l * gpl + q;
            if (g < NG) {
                sbase[g] = run;
                run += __popc(smask[g]);
            }
        }
        if (l == 0) s_total = total;
    }
    __syncthreads();

    // Phase C: extract first-K indices
    const int total = s_total;
    for (int gi = 0; gi < gpw; gi++) {
        int g = w * gpw + gi;
        if (g < NG) {
            unsigned m = smask[g];
            int base = sbase[g];
            if (m != 0u && base < K) {
                if (m & (1u << l)) {
                    int pos = base + __popc(m & ((1u << l) - 1u));
                    if (pos < K) sIdx[pos] = (g << 5) + l;
                }
            }
        }
    }
    __syncthreads();
    const int fillv = (total > 0) ? sIdx[0] : 0;
    for (int k = total + tid; k < K; k += 256) sIdx[k] = fillv;
    __syncthreads();

    // gather
    const int C = 3 + Cf;
    const size_t SK = (size_t)S * K;
    const size_t pbase = (size_t)s * K;
    for (int e = tid; e < C * K; e += blockDim.x) {
        int ch = e / K, k = e - ch * K;
        int j = sIdx[k];
        float v;
        if (ch == 0)      v = __fsub_rn(px[j * 3 + 0], cx);
        else if (ch == 1) v = __fsub_rn(px[j * 3 + 1], cy);
        else if (ch == 2) v = __fsub_rn(px[j * 3 + 2], cz);
        else              v = feats[((size_t)b * Cf + (ch - 3)) * N + j];
        grp[((size_t)b * C + ch) * SK + pbase + k] = v;
    }
}

// ---------------- SA1 layer1: 9 -> 64 streaming conv + BN + ReLU ----------------
__global__ void conv9_kernel(const float* __restrict__ x, const float* __restrict__ W,
                             const float* __restrict__ g, const float* __restrict__ bi,
                             float* __restrict__ out, int P) {
    __shared__ float ws[64 * 9];
    __shared__ float gs[64], bs[64];
    const int tid = threadIdx.x;
    if (tid < 64) { gs[tid] = g[tid]; bs[tid] = bi[tid]; }
    for (int e = tid; e < 576; e += 256) ws[e] = W[e];
    __syncthreads();

    const int b = blockIdx.y;
    const int p = blockIdx.x * 256 + tid;
    const float* xb = x + (size_t)b * 9 * P;
    float xv[9];
#pragma unroll
    for (int c = 0; c < 9; c++) xv[c] = xb[(size_t)c * P + p];
    float* ob = out + (size_t)b * 64 * P;
#pragma unroll 8
    for (int o = 0; o < 64; o++) {
        float a = 0.f;
#pragma unroll
        for (int c = 0; c < 9; c++) a = fmaf(ws[o * 9 + c], xv[c], a);
        ob[(size_t)o * P + p] = fmaxf(fmaf(a, gs[o], bs[o]), 0.f);
    }
}

// ---------------- bf16 split-MMA GEMM: 64o x 128p block tile, K-chunk 16 -----------
template <int MAXPOOL>
__global__ __launch_bounds__(256, 2) void mma_gemm_kernel(
    const float* __restrict__ x, const __nv_bfloat16* __restrict__ Wh,
    const __nv_bfloat16* __restrict__ Wl, const float* __restrict__ g,
    const float* __restrict__ bi, float* __restrict__ out,
    int Cin, int Cpad, int Cout, int P, int S, int K) {
    __shared__ uint32_t sWh[2][64][12], sWl[2][64][12];
    __shared__ uint32_t sXh[128][12], sXl[128][12];
    __shared__ float red[4][64];

    const int b = blockIdx.z;
    const int o0 = blockIdx.y * 64;
    const int p0 = blockIdx.x * 128;
    const int tid = threadIdx.x;
    const int w = tid >> 5, l = tid & 31;
    const int gq = l >> 2, tq = l & 3;
    const int wm = w & 1, wn = w >> 1;

    const float* xb = x + (size_t)b * Cin * P;
    const int nch = (Cin + 15) >> 4;

    float acc[2][4][4];
#pragma unroll
    for (int i = 0; i < 2; i++)
#pragma unroll
        for (int j = 0; j < 4; j++)
#pragma unroll
            for (int r = 0; r < 4; r++) acc[i][j][r] = 0.f;

    auto stage_w = [&](int c0, int buf) {
        int which = tid & 1, r = (tid >> 1) & 63, half = (tid >> 7) & 1;
        const __nv_bfloat16* src =
            (which ? Wl : Wh) + (size_t)(o0 + r) * Cpad + c0 + half * 8;
        uint32_t dst = smem_u32(which ? &sWl[buf][r][half * 4] : &sWh[buf][r][half * 4]);
        cp16(dst, src);
    };
    const int xp = tid & 127;
    const int xch = (tid >> 7) * 8;
    auto load_x = [&](int c0, float xr[8]) {
        bool pv = (p0 + xp) < P;
#pragma unroll
        for (int q = 0; q < 8; q++) {
            int cc = c0 + xch + q;
            xr[q] = (pv && cc < Cin) ? xb[(size_t)cc * P + p0 + xp] : 0.f;
        }
    };
    auto store_x = [&](const float xr[8]) {
        uint32_t hq[4], lq[4];
#pragma unroll
        for (int k = 0; k < 4; k++) {
            float a = xr[2 * k], c = xr[2 * k + 1];
            __nv_bfloat16 ah = __float2bfloat16(a), ch = __float2bfloat16(c);
            float al = a - __bfloat162float(ah), cl = c - __bfloat162float(ch);
            hq[k] = (uint32_t)__bfloat16_as_ushort(ah) |
                    ((uint32_t)__bfloat16_as_ushort(ch) << 16);
            lq[k] = (uint32_t)__bfloat16_as_ushort(__float2bfloat16(al)) |
                    ((uint32_t)__bfloat16_as_ushort(__float2bfloat16(cl)) << 16);
        }
        *(uint4*)&sXh[xp][(xch >> 1)] = make_uint4(hq[0], hq[1], hq[2], hq[3]);
        *(uint4*)&sXl[xp][(xch >> 1)] = make_uint4(lq[0], lq[1], lq[2], lq[3]);
    };

    float xr[8], xr2[8];
    load_x(0, xr);
    stage_w(0, 0);
    cp_commit();

    for (int c = 0; c < nch; c++) {
        __syncthreads();
        store_x(xr);
        if (c + 1 < nch) {
            load_x((c + 1) * 16, xr2);
            stage_w((c + 1) * 16, (c + 1) & 1);
            cp_commit();
            cp_wait<1>();
        } else {
            cp_wait<0>();
        }
        __syncthreads();

        const uint32_t(*wh)[12] = sWh[c & 1];
        const uint32_t(*wl)[12] = sWl[c & 1];
        uint32_t ah[2][4], al[2][4], bh[4][2], bl[4][2];
#pragma unroll
        for (int i = 0; i < 2; i++) {
            int ro = wm * 32 + i * 16;
            ah[i][0] = wh[ro + gq][tq];
            ah[i][1] = wh[ro + gq + 8][tq];
            ah[i][2] = wh[ro + gq][tq + 4];
            ah[i][3] = wh[ro + gq + 8][tq + 4];
            al[i][0] = wl[ro + gq][tq];
            al[i][1] = wl[ro + gq + 8][tq];
            al[i][2] = wl[ro + gq][tq + 4];
            al[i][3] = wl[ro + gq + 8][tq + 4];
        }
#pragma unroll
        for (int j = 0; j < 4; j++) {
            int rp = wn * 32 + j * 8 + gq;
            bh[j][0] = sXh[rp][tq];
            bh[j][1] = sXh[rp][tq + 4];
            bl[j][0] = sXl[rp][tq];
            bl[j][1] = sXl[rp][tq + 4];
        }
#pragma unroll
        for (int i = 0; i < 2; i++)
#pragma unroll
            for (int j = 0; j < 4; j++) {
                mma16816(acc[i][j], ah[i], bh[j]);
                mma16816(acc[i][j], ah[i], bl[j]);
                mma16816(acc[i][j], al[i], bh[j]);
            }
        if (c + 1 < nch) {
#pragma unroll
            for (int q = 0; q < 8; q++) xr[q] = xr2[q];
        }
    }

#pragma unroll
    for (int i = 0; i < 2; i++) {
#pragma unroll
        for (int half = 0; half < 2; half++) {
            int orow = o0 + wm * 32 + i * 16 + gq + half * 8;
            float gv = g[orow], bv = bi[orow];
            if (MAXPOOL == 0) {
                float* ob = out + (size_t)b * Cout * P + (size_t)orow * P;
#pragma unroll
                for (int j = 0; j < 4; j++) {
                    int pb = p0 + wn * 32 + j * 8 + 2 * tq;
                    float v0 = fmaxf(fmaf(acc[i][j][half * 2], gv, bv), 0.f);
                    float v1 = fmaxf(fmaf(acc[i][j][half * 2 + 1], gv, bv), 0.f);
                    if (pb < P) ob[pb] = v0;
                    if (pb + 1 < P) ob[pb + 1] = v1;
                }
            } else {
                float m = 0.f;
#pragma unroll
                for (int j = 0; j < 4; j++) {
                    m = fmaxf(m, fmaxf(fmaf(acc[i][j][half * 2], gv, bv),
                                       fmaf(acc[i][j][half * 2 + 1], gv, bv)));
                }
                m = fmaxf(m, 0.f);
                m = fmaxf(m, __shfl_xor_sync(0xffffffffu, m, 1));
                m = fmaxf(m, __shfl_xor_sync(0xffffffffu, m, 2));
                if (tq == 0) red[wn][wm * 32 + i * 16 + half * 8 + gq] = m;
            }
        }
    }
    if (MAXPOOL == 1) {
        __syncthreads();
        if (K == 32) {
            int o = tid & 63, grp = tid >> 6;
            if (p0 + grp * 32 < P)
                out[((size_t)b * Cout + o0 + o) * S + (p0 >> 5) + grp] = red[grp][o];
        } else {
            if (tid < 128) {
                int o = tid & 63, grp = tid >> 6;
                if (p0 + grp * 64 < P) {
                    float m = fmaxf(red[2 * grp][o], red[2 * grp + 1][o]);
                    out[((size_t)b * Cout + o0 + o) * S + (p0 >> 6) + grp] = m;
                }
            }
        }
    }
}

// ---------------- dense layer on [B, Cin] vectors (classifier head) ----------------
__global__ void dense_kernel(const float* __restrict__ x, const float* __restrict__ W,
                             const float* __restrict__ g, const float* __restrict__ bi,
                             float* __restrict__ out, int Cin, int Cout, int do_relu) {
    const int b = blockIdx.x;
    const int o = blockIdx.y * 8 + (threadIdx.x >> 5);
    const int lane = threadIdx.x & 31;
    if (o >= Cout) return;
    const float* xb = x + (size_t)b * Cin;
    float acc = 0.f;
    for (int c = lane; c < Cin; c += 32)
        acc = fmaf(W[(size_t)o * Cin + c], xb[c], acc);
#pragma unroll
    for (int off = 16; off; off >>= 1)
        acc += __shfl_xor_sync(0xffffffffu, acc, off);
    if (lane == 0) {
        float v = g ? fmaf(acc, g[o], bi[o]) : (acc + bi[o]);
        if (do_relu) v = fmaxf(v, 0.f);
        out[(size_t)b * Cout + o] = v;
    }
}

// ---------------- launch ----------------
extern "C" void kernel_launch(void* const* d_in, const int* in_sizes, int n_in,
                              void* d_out, int out_size) {
    const float* pc = (const float*)d_in[0];
    const float* saw[3][2];
    const float* sag[3][2];
    const float* sab[3][2];
    for (int sm = 0; sm < 3; sm++)
        for (int l = 0; l < 2; l++) {
            int base = 1 + sm * 6 + l * 3;
            saw[sm][l] = (const float*)d_in[base + 0];
            sag[sm][l] = (const float*)d_in[base + 1];
            sab[sm][l] = (const float*)d_in[base + 2];
        }
    const float* clsw[4];
    const float* clsg[3];
    const float* clsb[4];
    for (int l = 0; l < 3; l++) {
        clsw[l] = (const float*)d_in[19 + l * 3 + 0];
        clsg[l] = (const float*)d_in[19 + l * 3 + 1];
        clsb[l] = (const float*)d_in[19 + l * 3 + 2];
    }
    clsw[3] = (const float*)d_in[28];
    clsb[3] = (const float*)d_in[29];

    float *xyz1, *feat1, *xyz2, *grp1, *h1, *feat2, *xyz3, *grp2, *h2, *feat3;
    float *xyz4, *grp3, *h3, *feat4, *c1, *c2, *c3;
    int *sidx1, *sidx2, *sidx3;
    __nv_bfloat16 *wh, *wl;
    cudaGetSymbolAddress((void**)&xyz1, g_xyz1);
    cudaGetSymbolAddress((void**)&feat1, g_feat1);
    cudaGetSymbolAddress((void**)&sidx1, g_sidx1);
    cudaGetSymbolAddress((void**)&xyz2, g_xyz2);
    cudaGetSymbolAddress((void**)&grp1, g_grp1);
    cudaGetSymbolAddress((void**)&h1, g_h1);
    cudaGetSymbolAddress((void**)&feat2, g_feat2);
    cudaGetSymbolAddress((void**)&sidx2, g_sidx2);
    cudaGetSymbolAddress((void**)&xyz3, g_xyz3);
    cudaGetSymbolAddress((void**)&grp2, g_grp2);
    cudaGetSymbolAddress((void**)&h2, g_h2);
    cudaGetSymbolAddress((void**)&feat3, g_feat3);
    cudaGetSymbolAddress((void**)&sidx3, g_sidx3);
    cudaGetSymbolAddress((void**)&xyz4, g_xyz4);
    cudaGetSymbolAddress((void**)&grp3, g_grp3);
    cudaGetSymbolAddress((void**)&h3, g_h3);
    cudaGetSymbolAddress((void**)&feat4, g_feat4);
    cudaGetSymbolAddress((void**)&c1, g_c1);
    cudaGetSymbolAddress((void**)&c2, g_c2);
    cudaGetSymbolAddress((void**)&c3, g_c3);
    cudaGetSymbolAddress((void**)&wh, g_wh);
    cudaGetSymbolAddress((void**)&wl, g_wl);

    prep_w_kernel<<<(722944 + 255) / 256, 256>>>(saw[0][1], saw[1][0], saw[1][1],
                                                 saw[2][0], saw[2][1]);
    split_kernel<<<(BB * NPTS + 255) / 256, 256>>>(pc, xyz1, feat1);

    // ---- SA1: N=4096 -> S=512, K=32, r=0.1, C: 9 -> 64 -> 128 ----
    fps_kernel<<<BB, 1024>>>(xyz1, NPTS, 512, sidx1);
    bq_group_kernel<<<dim3(512, BB), 256>>>(xyz1, sidx1, feat1, xyz2, grp1,
                                            NPTS, 512, 32, 6, (float)(0.1 * 0.1));
    conv9_kernel<<<dim3(16384 / 256, BB), 256>>>(
        grp1, saw[0][0], sag[0][0], sab[0][0], h1, 16384);
    mma_gemm_kernel<1><<<dim3(16384 / 128, 2, BB), 256>>>(
        h1, wh + WO0, wl + WO0, sag[0][1], sab[0][1], feat2,
        64, 64, 128, 16384, 512, 32);

    // ---- SA2: N=512 -> S=64, K=64, r=0.2, C: 131 -> 128 -> 256 ----
    fps_kernel<<<BB, 1024>>>(xyz2, 512, 64, sidx2);
    bq_group_kernel<<<dim3(64, BB), 256>>>(xyz2, sidx2, feat2, xyz3, grp2,
                                           512, 64, 64, 128, (float)(0.2 * 0.2));
    mma_gemm_kernel<0><<<dim3(4096 / 128, 2, BB), 256>>>(
        grp2, wh + WO1, wl + WO1, sag[1][0], sab[1][0], h2,
        131, 144, 128, 4096, 1, 1);
    mma_gemm_kernel<1><<<dim3(4096 / 128, 4, BB), 256>>>(
        h2, wh + WO2, wl + WO2, sag[1][1], sab[1][1], feat3,
        128, 128, 256, 4096, 64, 64);

    // ---- SA3: N=64 -> S=1, K=64, r=0.4, C: 259 -> 512 -> 1024 ----
    fps_kernel<<<BB, 1024>>>(xyz3, 64, 1, sidx3);
    bq_group_kernel<<<dim3(1, BB), 256>>>(xyz3, sidx3, feat3, xyz4, grp3,
                                          64, 1, 64, 256, (float)(0.4 * 0.4));
    mma_gemm_kernel<0><<<dim3(1, 8, BB), 256>>>(
        grp3, wh + WO3, wl + WO3, sag[2][0], sab[2][0], h3,
        259, 272, 512, 64, 1, 1);
    mma_gemm_kernel<1><<<dim3(1, 16, BB), 256>>>(
        h3, wh + WO4, wl + WO4, sag[2][1], sab[2][1], feat4,
        512, 512, 1024, 64, 1, 64);

    // ---- classifier head on [B, 1024] ----
    dense_kernel<<<dim3(BB, 1024 / 8), 256>>>(feat4, clsw[0], clsg[0], clsb[0], c1, 1024, 1024, 1);
    dense_kernel<<<dim3(BB, 512 / 8), 256>>>(c1, clsw[1], clsg[1], clsb[1], c2, 1024, 512, 1);
    dense_kernel<<<dim3(BB, 128 / 8), 256>>>(c2, clsw[2], clsg[2], clsb[2], c3, 512, 128, 1);
    dense_kernel<<<dim3(BB, (63 + 7) / 8), 256>>>(c3, clsw[3], nullptr, clsb[3],
                                                  (float*)d_out, 128, 63, 0);
}